// round 5
// baseline (speedup 1.0000x reference)
#include <cuda_runtime.h>
#include <cuda_fp16.h>
#include <cstdint>
#include <math.h>

// ---------------- problem constants ----------------
#define BB 8
#define NN 2048
#define FF 64
#define FHD 64
#define HH 4

#define TIx 64            // rows per CTA
#define TJx 64            // j per tile
#define NJT (NN / TJx)    // 32 j-tiles
#define THR2 256          // k_attn threads (8 warps)

// ---------------- scratch ----------------
__device__ __half g_feats16[(size_t)BB * HH * NN * FHD]; // [b][h][n][o] fp16
__device__ float2 g_EG[BB * HH * NN];  // (exp(ss), exp(0.2 ss))
__device__ float2 g_FH[BB * HH * NN];  // (exp(sn), exp(0.2 sn))
__device__ float  g_wa[2 * HH * FF];   // [which][h][f]

// ---------------- helpers ----------------
__device__ __forceinline__ uint32_t smem_u32(const void* p) {
    uint32_t a;
    asm("{ .reg .u64 t; cvta.to.shared.u64 t, %1; cvt.u32.u64 %0, t; }" : "=r"(a) : "l"(p));
    return a;
}
#define CP_ASYNC16(dst, src) \
    asm volatile("cp.async.cg.shared.global [%0], [%1], 16;" :: "r"(dst), "l"(src) : "memory")
#define CP_COMMIT() asm volatile("cp.async.commit_group;" ::: "memory")
#define CP_WAIT(n)  asm volatile("cp.async.wait_group %0;" :: "n"(n) : "memory")

__device__ __forceinline__ void ldmx4t(uint32_t* r, uint32_t addr) {
    asm volatile("ldmatrix.sync.aligned.m8n8.x4.trans.shared.b16 {%0,%1,%2,%3}, [%4];"
                 : "=r"(r[0]), "=r"(r[1]), "=r"(r[2]), "=r"(r[3]) : "r"(addr));
}
__device__ __forceinline__ void mma16816(float* c, const uint32_t* a, uint32_t b0, uint32_t b1) {
    asm volatile(
        "mma.sync.aligned.m16n8k16.row.col.f32.f16.f16.f32 "
        "{%0,%1,%2,%3},{%4,%5,%6,%7},{%8,%9},{%0,%1,%2,%3};"
        : "+f"(c[0]), "+f"(c[1]), "+f"(c[2]), "+f"(c[3])
        : "r"(a[0]), "r"(a[1]), "r"(a[2]), "r"(a[3]), "r"(b0), "r"(b1));
}

// ---------------- smem layout per buffer (bytes) ----------------
// V: [4][64][72] half (144B pitch, conflict-free ldmatrix), FH: [4][64] float2
#define OFF_V   0
#define OFF_FH  36864
#define BUFSZ   38912
#define SMEM_SZ (2 * BUFSZ)   // 77824 B -> 2 CTAs/SM (155.6KB < 228KB)

// ==================== Kernel 0: wa = W . a (coalesced, multi-CTA) ====================
__global__ __launch_bounds__(256) void k_prep(
    const float* __restrict__ W, const float* __restrict__ a_self,
    const float* __restrict__ a_neigh) {
    const int lane = threadIdx.x & 31, wid = threadIdx.x >> 5;
    const int base = blockIdx.x * 32 + wid * 4;   // 16 blocks x 8 warps x 4 outputs
#pragma unroll
    for (int u = 0; u < 4; ++u) {
        int idx = base + u;
        int which = idx >> 8, hf = idx & 255, h = hf >> 6;
        const float* ap = (which ? a_neigh : a_self) + h * 64;
        const float* wrow = W + (size_t)hf * 64;
        float s = wrow[lane] * ap[lane] + wrow[lane + 32] * ap[lane + 32];
#pragma unroll
        for (int d = 16; d > 0; d >>= 1) s += __shfl_xor_sync(0xffffffffu, s, d);
        if (lane == 0) g_wa[idx] = s;
    }
}

// ==================== Kernel 1: feats (fp16) + E/G/F/H ====================
__global__ __launch_bounds__(256) void k_feats(
    const float* __restrict__ X, const float* __restrict__ W) {
    const int ROWS = 16;
    int bi = blockIdx.x;
    int b  = bi >> 7;
    int n0 = (bi & 127) * ROWS;
    int t = threadIdx.x;
    int h = t >> 6, o = t & 63;

    __shared__ float X_s[ROWS * 64];
    __shared__ __half F_s[ROWS][256];

    for (int idx = t; idx < ROWS * 64; idx += 256)
        X_s[idx] = X[(size_t)(b * NN + n0 + (idx >> 6)) * FF + (idx & 63)];

    float w_reg[64];
#pragma unroll
    for (int f = 0; f < 64; ++f) w_reg[f] = W[(h * 64 + f) * 64 + o];
    __syncthreads();

#pragma unroll
    for (int r = 0; r < ROWS; ++r) {
        float acc = 0.f;
#pragma unroll
        for (int f = 0; f < 64; ++f) acc += X_s[r * 64 + f] * w_reg[f];
        F_s[r][h * 64 + o] = __float2half(acc);
    }

    if (t < 128) {
        int r = t >> 3, hh = (t >> 1) & 3, wh = t & 1;
        const float* wap = g_wa + wh * 256 + hh * 64;
        float s = 0.f;
#pragma unroll
        for (int f = 0; f < 64; ++f) s += X_s[r * 64 + f] * wap[f];
        float2 eg = make_float2(__expf(s), __expf(0.2f * s));
        (wh ? g_FH : g_EG)[(size_t)(b * HH + hh) * NN + n0 + r] = eg;
    }
    __syncthreads();

#pragma unroll
    for (int k = 0; k < 2; ++k) {
        int e = t + k * 256;
        int r = e >> 5, c = (e & 31) * 8;
        int hh = c >> 6, o0 = c & 63;
        uint4 v = *reinterpret_cast<const uint4*>(&F_s[r][c]);
        *reinterpret_cast<uint4*>(
            &g_feats16[((size_t)(b * HH + hh) * NN + n0 + r) * FHD + o0]) = v;
    }
}

// ==================== Kernel 2: flash-GAT via mma.sync ====================
extern __shared__ char smem[];

__global__ __launch_bounds__(THR2, 2) void k_attn(
    const float* __restrict__ A, const float* __restrict__ bias,
    float* __restrict__ out) {
    const int b  = blockIdx.y;
    const int i0 = blockIdx.x * TIx;
    const int t = threadIdx.x, lane = t & 31, wid = t >> 5;
    const int h = wid >> 1;            // head
    const int rbase = (wid & 1) * 32;  // warp owns 32 rows
    const int g = lane >> 2;           // frag row group 0..7
    const int q = lane & 3;            // frag col group 0..3
    const uint32_t sb = smem_u32(smem);

    auto issue_tile = [&](int jt, int buf) {
        const uint32_t base = sb + buf * BUFSZ;
        const int j0 = jt * TJx;
#pragma unroll
        for (int k = 0; k < 8; ++k) {            // V: 4x64x64 half
            int e = t + k * 256;
            int hh = e >> 9, j = (e >> 3) & 63, o8 = e & 7;
            CP_ASYNC16(base + OFF_V + hh * 9216 + j * 144 + o8 * 16,
                       &g_feats16[((size_t)(b * HH + hh) * NN + j0 + j) * FHD + o8 * 8]);
        }
        if (t < 128) {                           // FH: 4x64 float2
            int hh = t >> 5, jj = (t & 31) * 2;
            CP_ASYNC16(base + OFF_FH + hh * 512 + jj * 8,
                       &g_FH[(size_t)(b * HH + hh) * NN + j0 + jj]);
        }
        CP_COMMIT();
    };

    // A row base pointers for this thread's 4 frag rows
    const float* Ar[2][2];
#pragma unroll
    for (int m = 0; m < 2; ++m)
#pragma unroll
        for (int hi = 0; hi < 2; ++hi)
            Ar[m][hi] = A + (size_t)(b * NN + i0 + rbase + m * 16 + g + hi * 8) * NN;

    // per-thread row constants: E, G for 4 rows
    float Er[2][2], Gr[2][2];
#pragma unroll
    for (int m = 0; m < 2; ++m)
#pragma unroll
        for (int hi = 0; hi < 2; ++hi) {
            float2 eg = g_EG[(size_t)(b * HH + h) * NN + i0 + rbase + m * 16 + g + hi * 8];
            Er[m][hi] = eg.x;
            Gr[m][hi] = eg.y;
        }

    float acc[2][8][4];
#pragma unroll
    for (int m = 0; m < 2; ++m)
#pragma unroll
        for (int n = 0; n < 8; ++n)
#pragma unroll
            for (int c = 0; c < 4; ++c) acc[m][n][c] = 0.f;

    float rsum[2][2] = {{0.f, 0.f}, {0.f, 0.f}};

    issue_tile(0, 0);

    const int rowlane = lane & 15, colsel = lane >> 4;

#pragma unroll 1
    for (int jt = 0; jt < NJT; ++jt) {
        const int buf = jt & 1;
        const int j0 = jt * TJx;
        if (jt + 1 < NJT) { issue_tile(jt + 1, buf ^ 1); CP_WAIT(1); }
        else             { CP_WAIT(0); }
        __syncthreads();

        const float2* FHh = (const float2*)(smem + buf * BUFSZ + OFF_FH) + h * 64;
        const uint32_t sbVh = sb + buf * BUFSZ + OFF_V + h * 9216;

#pragma unroll
        for (int k = 0; k < 4; ++k) {
            const int jc = k * 16 + q * 2;

            // ---- A direct from global (sector-exact, L1-reused across heads) ----
            float2 a00 = __ldg((const float2*)(Ar[0][0] + j0 + jc));
            float2 a01 = __ldg((const float2*)(Ar[0][1] + j0 + jc));
            float2 a08 = __ldg((const float2*)(Ar[0][0] + j0 + jc + 8));
            float2 a09 = __ldg((const float2*)(Ar[0][1] + j0 + jc + 8));
            float2 a10 = __ldg((const float2*)(Ar[1][0] + j0 + jc));
            float2 a11 = __ldg((const float2*)(Ar[1][1] + j0 + jc));
            float2 a18 = __ldg((const float2*)(Ar[1][0] + j0 + jc + 8));
            float2 a19 = __ldg((const float2*)(Ar[1][1] + j0 + jc + 8));

            float2 fh0 = FHh[jc], fh1 = FHh[jc + 1];
            float2 fh8 = FHh[jc + 8], fh9 = FHh[jc + 9];

            uint32_t afr[2][4];
#pragma unroll
            for (int m = 0; m < 2; ++m) {
                float El = Er[m][0], Gl = Gr[m][0], Eh = Er[m][1], Gh = Gr[m][1];
                float2 alo0 = (m == 0) ? a00 : a10;
                float2 ahi0 = (m == 0) ? a01 : a11;
                float2 alo8 = (m == 0) ? a08 : a18;
                float2 ahi8 = (m == 0) ? a09 : a19;

                float p00 = fmaxf(El * fh0.x, Gl * fh0.y) * alo0.x;
                float p01 = fmaxf(El * fh1.x, Gl * fh1.y) * alo0.y;
                float p10 = fmaxf(Eh * fh0.x, Gh * fh0.y) * ahi0.x;
                float p11 = fmaxf(Eh * fh1.x, Gh * fh1.y) * ahi0.y;
                float p08 = fmaxf(El * fh8.x, Gl * fh8.y) * alo8.x;
                float p09 = fmaxf(El * fh9.x, Gl * fh9.y) * alo8.y;
                float p18 = fmaxf(Eh * fh8.x, Gh * fh8.y) * ahi8.x;
                float p19 = fmaxf(Eh * fh9.x, Gh * fh9.y) * ahi8.y;

                rsum[m][0] += (p00 + p01) + (p08 + p09);
                rsum[m][1] += (p10 + p11) + (p18 + p19);

                __half2 h0 = __floats2half2_rn(p00, p01);
                __half2 h1 = __floats2half2_rn(p10, p11);
                __half2 h2v = __floats2half2_rn(p08, p09);
                __half2 h3 = __floats2half2_rn(p18, p19);
                afr[m][0] = *reinterpret_cast<uint32_t*>(&h0);
                afr[m][1] = *reinterpret_cast<uint32_t*>(&h1);
                afr[m][2] = *reinterpret_cast<uint32_t*>(&h2v);
                afr[m][3] = *reinterpret_cast<uint32_t*>(&h3);
            }

            // ---- immediately consume this k-step: ldmatrix + HMMA ----
#pragma unroll
            for (int n = 0; n < 4; ++n) {
                uint32_t bfr[4];
                ldmx4t(bfr, sbVh + (k * 16 + rowlane) * 144 + (n * 16 + colsel * 8) * 2);
#pragma unroll
                for (int m = 0; m < 2; ++m) {
                    mma16816(acc[m][2 * n],     afr[m], bfr[0], bfr[1]);
                    mma16816(acc[m][2 * n + 1], afr[m], bfr[2], bfr[3]);
                }
            }
        }
        __syncthreads();
    }

    // ---- reduce row sums across the 4 lanes sharing a row ----
    float inv[2][2];
#pragma unroll
    for (int m = 0; m < 2; ++m)
#pragma unroll
        for (int hi = 0; hi < 2; ++hi) {
            float r = rsum[m][hi];
            r += __shfl_xor_sync(0xffffffffu, r, 1);
            r += __shfl_xor_sync(0xffffffffu, r, 2);
            inv[m][hi] = 1.f / r;
        }

    // ---- epilogue: normalize + bias + relu ----
#pragma unroll
    for (int n = 0; n < 8; ++n) {
        const int col = h * 64 + n * 8 + q * 2;
        float2 bv = *reinterpret_cast<const float2*>(&bias[col]);
#pragma unroll
        for (int m = 0; m < 2; ++m) {
            const int rlo = i0 + rbase + m * 16 + g;
            float2 lo, hi2;
            lo.x  = fmaxf(acc[m][n][0] * inv[m][0] + bv.x, 0.f);
            lo.y  = fmaxf(acc[m][n][1] * inv[m][0] + bv.y, 0.f);
            hi2.x = fmaxf(acc[m][n][2] * inv[m][1] + bv.x, 0.f);
            hi2.y = fmaxf(acc[m][n][3] * inv[m][1] + bv.y, 0.f);
            *reinterpret_cast<float2*>(&out[((size_t)(b * NN + rlo)) * 256 + col]) = lo;
            *reinterpret_cast<float2*>(&out[((size_t)(b * NN + rlo + 8)) * 256 + col]) = hi2;
        }
    }
}

// ==================== launch ====================
extern "C" void kernel_launch(void* const* d_in, const int* in_sizes, int n_in,
                              void* d_out, int out_size) {
    const float* X       = (const float*)d_in[0];
    const float* A       = (const float*)d_in[1];
    const float* W       = (const float*)d_in[2];
    const float* bias    = (const float*)d_in[3];
    const float* a_self  = (const float*)d_in[4];
    const float* a_neigh = (const float*)d_in[5];
    float* out = (float*)d_out;

    static bool attr_set = false;
    if (!attr_set) {
        cudaFuncSetAttribute(k_attn, cudaFuncAttributeMaxDynamicSharedMemorySize, SMEM_SZ);
        attr_set = true;
    }

    k_prep<<<16, 256>>>(W, a_self, a_neigh);
    k_feats<<<BB * NN / 16, 256>>>(X, W);
    dim3 grid2(NN / TIx, BB);
    k_attn<<<grid2, THR2, SMEM_SZ>>>(A, bias, out);
}

// round 6
// speedup vs baseline: 1.0208x; 1.0208x over previous
#include <cuda_runtime.h>
#include <cuda_fp16.h>
#include <cstdint>
#include <math.h>

// ---------------- problem constants ----------------
#define BB 8
#define NN 2048
#define FF 64
#define FHD 64
#define HH 4

#define TIx 128           // rows per CTA
#define TJx 64            // j per tile
#define NJT (NN / TJx)    // 32 j-tiles
#define THR2 512          // k_attn threads (16 warps)

// ---------------- scratch ----------------
__device__ __half g_feats16[(size_t)BB * HH * NN * FHD]; // [b][h][n][o] fp16
__device__ float2 g_EG[BB * HH * NN];  // (exp(ss), exp(0.2 ss))
__device__ float2 g_FH[BB * HH * NN];  // (exp(sn), exp(0.2 sn))
__device__ float  g_wa[2 * HH * FF];   // [which][h][f]

// ---------------- helpers ----------------
__device__ __forceinline__ uint32_t smem_u32(const void* p) {
    uint32_t a;
    asm("{ .reg .u64 t; cvta.to.shared.u64 t, %1; cvt.u32.u64 %0, t; }" : "=r"(a) : "l"(p));
    return a;
}
#define CP_ASYNC16(dst, src) \
    asm volatile("cp.async.cg.shared.global [%0], [%1], 16;" :: "r"(dst), "l"(src) : "memory")
#define CP_COMMIT() asm volatile("cp.async.commit_group;" ::: "memory")
#define CP_WAIT(n)  asm volatile("cp.async.wait_group %0;" :: "n"(n) : "memory")

__device__ __forceinline__ void ldmx4t(uint32_t* r, uint32_t addr) {
    asm volatile("ldmatrix.sync.aligned.m8n8.x4.trans.shared.b16 {%0,%1,%2,%3}, [%4];"
                 : "=r"(r[0]), "=r"(r[1]), "=r"(r[2]), "=r"(r[3]) : "r"(addr));
}
__device__ __forceinline__ void mma16816(float* c, const uint32_t* a, uint32_t b0, uint32_t b1) {
    asm volatile(
        "mma.sync.aligned.m16n8k16.row.col.f32.f16.f16.f32 "
        "{%0,%1,%2,%3},{%4,%5,%6,%7},{%8,%9},{%0,%1,%2,%3};"
        : "+f"(c[0]), "+f"(c[1]), "+f"(c[2]), "+f"(c[3])
        : "r"(a[0]), "r"(a[1]), "r"(a[2]), "r"(a[3]), "r"(b0), "r"(b1));
}

// ---------------- smem layout per buffer (bytes) ----------------
// A:  [128][72] f32 (288B pitch)            -> 36864
// V:  [4][64][72] half (144B pitch)         -> 36864
// FH: [4][64] float2                        -> 2048
#define OFF_A   0
#define OFF_V   36864
#define OFF_FH  73728
#define BUFSZ   75776
#define SMEM_SZ (2 * BUFSZ)   // 151552 B -> 1 CTA/SM, 16 warps

// ==================== Kernel 0: wa = W . a (coalesced, multi-CTA) ====================
__global__ __launch_bounds__(256) void k_prep(
    const float* __restrict__ W, const float* __restrict__ a_self,
    const float* __restrict__ a_neigh) {
    const int lane = threadIdx.x & 31, wid = threadIdx.x >> 5;
    const int base = blockIdx.x * 32 + wid * 4;
#pragma unroll
    for (int u = 0; u < 4; ++u) {
        int idx = base + u;
        int which = idx >> 8, hf = idx & 255, h = hf >> 6;
        const float* ap = (which ? a_neigh : a_self) + h * 64;
        const float* wrow = W + (size_t)hf * 64;
        float s = wrow[lane] * ap[lane] + wrow[lane + 32] * ap[lane + 32];
#pragma unroll
        for (int d = 16; d > 0; d >>= 1) s += __shfl_xor_sync(0xffffffffu, s, d);
        if (lane == 0) g_wa[idx] = s;
    }
}

// ==================== Kernel 1: feats (fp16) + E/G/F/H ====================
__global__ __launch_bounds__(256) void k_feats(
    const float* __restrict__ X, const float* __restrict__ W) {
    const int ROWS = 16;
    int bi = blockIdx.x;
    int b  = bi >> 7;
    int n0 = (bi & 127) * ROWS;
    int t = threadIdx.x;
    int h = t >> 6, o = t & 63;

    __shared__ float X_s[ROWS * 64];
    __shared__ __half F_s[ROWS][256];

    for (int idx = t; idx < ROWS * 64; idx += 256)
        X_s[idx] = X[(size_t)(b * NN + n0 + (idx >> 6)) * FF + (idx & 63)];

    float w_reg[64];
#pragma unroll
    for (int f = 0; f < 64; ++f) w_reg[f] = W[(h * 64 + f) * 64 + o];
    __syncthreads();

#pragma unroll
    for (int r = 0; r < ROWS; ++r) {
        float acc = 0.f;
#pragma unroll
        for (int f = 0; f < 64; ++f) acc += X_s[r * 64 + f] * w_reg[f];
        F_s[r][h * 64 + o] = __float2half(acc);
    }

    if (t < 128) {
        int r = t >> 3, hh = (t >> 1) & 3, wh = t & 1;
        const float* wap = g_wa + wh * 256 + hh * 64;
        float s = 0.f;
#pragma unroll
        for (int f = 0; f < 64; ++f) s += X_s[r * 64 + f] * wap[f];
        float2 eg = make_float2(__expf(s), __expf(0.2f * s));
        (wh ? g_FH : g_EG)[(size_t)(b * HH + hh) * NN + n0 + r] = eg;
    }
    __syncthreads();

#pragma unroll
    for (int k = 0; k < 2; ++k) {
        int e = t + k * 256;
        int r = e >> 5, c = (e & 31) * 8;
        int hh = c >> 6, o0 = c & 63;
        uint4 v = *reinterpret_cast<const uint4*>(&F_s[r][c]);
        *reinterpret_cast<uint4*>(
            &g_feats16[((size_t)(b * HH + hh) * NN + n0 + r) * FHD + o0]) = v;
    }
}

// ==================== Kernel 2: flash-GAT via mma.sync ====================
extern __shared__ char smem[];

__global__ __launch_bounds__(THR2, 1) void k_attn(
    const float* __restrict__ A, const float* __restrict__ bias,
    float* __restrict__ out) {
    const int b  = blockIdx.y;
    const int i0 = blockIdx.x * TIx;
    const int t = threadIdx.x, lane = t & 31, wid = t >> 5;
    const int h = wid >> 2;            // head (4 warps per head)
    const int rbase = (wid & 3) * 32;  // warp owns 32 rows of 128
    const int g = lane >> 2;           // frag row group 0..7
    const int q = lane & 3;            // frag col group 0..3
    const uint32_t sb = smem_u32(smem);

    auto issue_tile = [&](int jt, int buf) {
        const uint32_t base = sb + buf * BUFSZ;
        const int j0 = jt * TJx;
#pragma unroll
        for (int k = 0; k < 4; ++k) {            // A: 128x64 f32
            int e = t + k * THR2;
            int r = e >> 4, c4 = e & 15;
            CP_ASYNC16(base + OFF_A + r * 288 + c4 * 16,
                       &A[((size_t)(b * NN + i0 + r)) * NN + j0 + c4 * 4]);
        }
#pragma unroll
        for (int k = 0; k < 4; ++k) {            // V: 4x64x64 half
            int e = t + k * THR2;
            int hh = e >> 9, j = (e >> 3) & 63, o8 = e & 7;
            CP_ASYNC16(base + OFF_V + hh * 9216 + j * 144 + o8 * 16,
                       &g_feats16[((size_t)(b * HH + hh) * NN + j0 + j) * FHD + o8 * 8]);
        }
        if (t < 128) {                           // FH: 4x64 float2
            int hh = t >> 5, jj = (t & 31) * 2;
            CP_ASYNC16(base + OFF_FH + hh * 512 + jj * 8,
                       &g_FH[(size_t)(b * HH + hh) * NN + j0 + jj]);
        }
        CP_COMMIT();
    };

    // per-thread row constants: E, G for 4 rows (m in {0,1} x lo/hi)
    float Er[2][2], Gr[2][2];
#pragma unroll
    for (int m = 0; m < 2; ++m)
#pragma unroll
        for (int hi = 0; hi < 2; ++hi) {
            float2 eg = g_EG[(size_t)(b * HH + h) * NN + i0 + rbase + m * 16 + g + hi * 8];
            Er[m][hi] = eg.x;
            Gr[m][hi] = eg.y;
        }

    float acc[2][8][4];
#pragma unroll
    for (int m = 0; m < 2; ++m)
#pragma unroll
        for (int n = 0; n < 8; ++n)
#pragma unroll
            for (int c = 0; c < 4; ++c) acc[m][n][c] = 0.f;

    float rsum[2][2] = {{0.f, 0.f}, {0.f, 0.f}};

    issue_tile(0, 0);

    const int rowlane = lane & 15, colsel = lane >> 4;

#pragma unroll 1
    for (int jt = 0; jt < NJT; ++jt) {
        const int buf = jt & 1;
        if (jt + 1 < NJT) { issue_tile(jt + 1, buf ^ 1); CP_WAIT(1); }
        else             { CP_WAIT(0); }
        __syncthreads();

        const float* As = (const float*)(smem + buf * BUFSZ + OFF_A);
        const float2* FHh = (const float2*)(smem + buf * BUFSZ + OFF_FH) + h * 64;
        const uint32_t sbVh = sb + buf * BUFSZ + OFF_V + h * 9216;

#pragma unroll
        for (int k = 0; k < 4; ++k) {
            const int jc = k * 16 + q * 2;
            float2 fh0 = FHh[jc], fh1 = FHh[jc + 1];
            float2 fh8 = FHh[jc + 8], fh9 = FHh[jc + 9];

            uint32_t afr[2][4];
#pragma unroll
            for (int m = 0; m < 2; ++m) {
                const int rlo = rbase + m * 16 + g;
                float2 alo0 = *(const float2*)(As + rlo * 72 + jc);
                float2 ahi0 = *(const float2*)(As + (rlo + 8) * 72 + jc);
                float2 alo8 = *(const float2*)(As + rlo * 72 + jc + 8);
                float2 ahi8 = *(const float2*)(As + (rlo + 8) * 72 + jc + 8);
                float El = Er[m][0], Gl = Gr[m][0], Eh = Er[m][1], Gh = Gr[m][1];

                float p00 = fmaxf(El * fh0.x, Gl * fh0.y) * alo0.x;
                float p01 = fmaxf(El * fh1.x, Gl * fh1.y) * alo0.y;
                float p10 = fmaxf(Eh * fh0.x, Gh * fh0.y) * ahi0.x;
                float p11 = fmaxf(Eh * fh1.x, Gh * fh1.y) * ahi0.y;
                float p08 = fmaxf(El * fh8.x, Gl * fh8.y) * alo8.x;
                float p09 = fmaxf(El * fh9.x, Gl * fh9.y) * alo8.y;
                float p18 = fmaxf(Eh * fh8.x, Gh * fh8.y) * ahi8.x;
                float p19 = fmaxf(Eh * fh9.x, Gh * fh9.y) * ahi8.y;

                rsum[m][0] += (p00 + p01) + (p08 + p09);
                rsum[m][1] += (p10 + p11) + (p18 + p19);

                __half2 h0 = __floats2half2_rn(p00, p01);
                __half2 h1 = __floats2half2_rn(p10, p11);
                __half2 h2v = __floats2half2_rn(p08, p09);
                __half2 h3 = __floats2half2_rn(p18, p19);
                afr[m][0] = *reinterpret_cast<uint32_t*>(&h0);
                afr[m][1] = *reinterpret_cast<uint32_t*>(&h1);
                afr[m][2] = *reinterpret_cast<uint32_t*>(&h2v);
                afr[m][3] = *reinterpret_cast<uint32_t*>(&h3);
            }

            // ---- immediately consume this k-step: ldmatrix + HMMA ----
#pragma unroll
            for (int n = 0; n < 4; ++n) {
                uint32_t bfr[4];
                ldmx4t(bfr, sbVh + (k * 16 + rowlane) * 144 + (n * 16 + colsel * 8) * 2);
#pragma unroll
                for (int m = 0; m < 2; ++m) {
                    mma16816(acc[m][2 * n],     afr[m], bfr[0], bfr[1]);
                    mma16816(acc[m][2 * n + 1], afr[m], bfr[2], bfr[3]);
                }
            }
        }
        __syncthreads();
    }

    // ---- reduce row sums across the 4 lanes sharing a row ----
    float inv[2][2];
#pragma unroll
    for (int m = 0; m < 2; ++m)
#pragma unroll
        for (int hi = 0; hi < 2; ++hi) {
            float r = rsum[m][hi];
            r += __shfl_xor_sync(0xffffffffu, r, 1);
            r += __shfl_xor_sync(0xffffffffu, r, 2);
            inv[m][hi] = 1.f / r;
        }

    // ---- epilogue: normalize + bias + relu ----
#pragma unroll
    for (int n = 0; n < 8; ++n) {
        const int col = h * 64 + n * 8 + q * 2;
        float2 bv = *reinterpret_cast<const float2*>(&bias[col]);
#pragma unroll
        for (int m = 0; m < 2; ++m) {
            const int rlo = i0 + rbase + m * 16 + g;
            float2 lo, hi2;
            lo.x  = fmaxf(acc[m][n][0] * inv[m][0] + bv.x, 0.f);
            lo.y  = fmaxf(acc[m][n][1] * inv[m][0] + bv.y, 0.f);
            hi2.x = fmaxf(acc[m][n][2] * inv[m][1] + bv.x, 0.f);
            hi2.y = fmaxf(acc[m][n][3] * inv[m][1] + bv.y, 0.f);
            *reinterpret_cast<float2*>(&out[((size_t)(b * NN + rlo)) * 256 + col]) = lo;
            *reinterpret_cast<float2*>(&out[((size_t)(b * NN + rlo + 8)) * 256 + col]) = hi2;
        }
    }
}

// ==================== launch ====================
extern "C" void kernel_launch(void* const* d_in, const int* in_sizes, int n_in,
                              void* d_out, int out_size) {
    const float* X       = (const float*)d_in[0];
    const float* A       = (const float*)d_in[1];
    const float* W       = (const float*)d_in[2];
    const float* bias    = (const float*)d_in[3];
    const float* a_self  = (const float*)d_in[4];
    const float* a_neigh = (const float*)d_in[5];
    float* out = (float*)d_out;

    static bool attr_set = false;
    if (!attr_set) {
        cudaFuncSetAttribute(k_attn, cudaFuncAttributeMaxDynamicSharedMemorySize, SMEM_SZ);
        attr_set = true;
    }

    k_prep<<<16, 256>>>(W, a_self, a_neigh);
    k_feats<<<BB * NN / 16, 256>>>(X, W);
    dim3 grid2(NN / TIx, BB);
    k_attn<<<grid2, THR2, SMEM_SZ>>>(A, bias, out);
}

// round 7
// speedup vs baseline: 1.4791x; 1.4489x over previous
#include <cuda_runtime.h>
#include <cuda_fp16.h>
#include <cstdint>
#include <math.h>

// ---------------- problem constants ----------------
#define BB 8
#define NN 2048
#define FF 64
#define FHD 64
#define HH 4

#define TIx 64            // rows per CTA
#define TJx 64            // j per tile
#define NJT (NN / TJx)    // 32 j-tiles
#define THR2 256          // k_attn threads (8 warps)

#define ONES2 0x3C003C00u // half2(1.0, 1.0)

// ---------------- scratch ----------------
__device__ __half g_feats16[(size_t)BB * HH * NN * FHD]; // [b][h][n][o] fp16
__device__ float2 g_EG[BB * HH * NN];  // (exp(ss), exp(0.2 ss))
__device__ float2 g_FH[BB * HH * NN];  // (exp(sn), exp(0.2 sn))
__device__ float  g_wa[2 * HH * FF];   // [which][h][f]

// ---------------- helpers ----------------
__device__ __forceinline__ uint32_t smem_u32(const void* p) {
    uint32_t a;
    asm("{ .reg .u64 t; cvta.to.shared.u64 t, %1; cvt.u32.u64 %0, t; }" : "=r"(a) : "l"(p));
    return a;
}
#define CP_ASYNC16(dst, src) \
    asm volatile("cp.async.cg.shared.global [%0], [%1], 16;" :: "r"(dst), "l"(src) : "memory")
#define CP_COMMIT() asm volatile("cp.async.commit_group;" ::: "memory")
#define CP_WAIT(n)  asm volatile("cp.async.wait_group %0;" :: "n"(n) : "memory")

__device__ __forceinline__ void ldmx4t(uint32_t* r, uint32_t addr) {
    asm volatile("ldmatrix.sync.aligned.m8n8.x4.trans.shared.b16 {%0,%1,%2,%3}, [%4];"
                 : "=r"(r[0]), "=r"(r[1]), "=r"(r[2]), "=r"(r[3]) : "r"(addr));
}
__device__ __forceinline__ void mma16816(float* c, const uint32_t* a, uint32_t b0, uint32_t b1) {
    asm volatile(
        "mma.sync.aligned.m16n8k16.row.col.f32.f16.f16.f32 "
        "{%0,%1,%2,%3},{%4,%5,%6,%7},{%8,%9},{%0,%1,%2,%3};"
        : "+f"(c[0]), "+f"(c[1]), "+f"(c[2]), "+f"(c[3])
        : "r"(a[0]), "r"(a[1]), "r"(a[2]), "r"(a[3]), "r"(b0), "r"(b1));
}

// ---------------- smem layout per buffer (bytes) ----------------
// A: [64][72] f32 (288B pitch), V: [4][64][72] half (144B pitch), FH: [4][64] float2
#define OFF_A   0
#define OFF_V   18432
#define OFF_FH  55296
#define BUFSZ   57344
#define SMEM_SZ (2 * BUFSZ)   // 114688 B -> 2 CTAs/SM (224KiB < 228KiB)

// ==================== Kernel 0: wa = W . a ====================
__global__ __launch_bounds__(256) void k_prep(
    const float* __restrict__ W, const float* __restrict__ a_self,
    const float* __restrict__ a_neigh) {
    const int lane = threadIdx.x & 31, wid = threadIdx.x >> 5;
    const int base = blockIdx.x * 32 + wid * 4;
#pragma unroll
    for (int u = 0; u < 4; ++u) {
        int idx = base + u;
        int which = idx >> 8, hf = idx & 255, h = hf >> 6;
        const float* ap = (which ? a_neigh : a_self) + h * 64;
        const float* wrow = W + (size_t)hf * 64;
        float s = wrow[lane] * ap[lane] + wrow[lane + 32] * ap[lane + 32];
#pragma unroll
        for (int d = 16; d > 0; d >>= 1) s += __shfl_xor_sync(0xffffffffu, s, d);
        if (lane == 0) g_wa[idx] = s;
    }
}

// ==================== Kernel 1: feats (fp16) + E/G/F/H ====================
__global__ __launch_bounds__(256) void k_feats(
    const float* __restrict__ X, const float* __restrict__ W) {
    const int ROWS = 16;
    int bi = blockIdx.x;
    int b  = bi >> 7;
    int n0 = (bi & 127) * ROWS;
    int t = threadIdx.x;
    int h = t >> 6, o = t & 63;

    __shared__ float X_s[ROWS * 64];
    __shared__ __half F_s[ROWS][256];

    for (int idx = t; idx < ROWS * 64; idx += 256)
        X_s[idx] = X[(size_t)(b * NN + n0 + (idx >> 6)) * FF + (idx & 63)];

    float w_reg[64];
#pragma unroll
    for (int f = 0; f < 64; ++f) w_reg[f] = W[(h * 64 + f) * 64 + o];
    __syncthreads();

#pragma unroll
    for (int r = 0; r < ROWS; ++r) {
        float acc = 0.f;
#pragma unroll
        for (int f = 0; f < 64; ++f) acc += X_s[r * 64 + f] * w_reg[f];
        F_s[r][h * 64 + o] = __float2half(acc);
    }

    if (t < 128) {
        int r = t >> 3, hh = (t >> 1) & 3, wh = t & 1;
        const float* wap = g_wa + wh * 256 + hh * 64;
        float s = 0.f;
#pragma unroll
        for (int f = 0; f < 64; ++f) s += X_s[r * 64 + f] * wap[f];
        float2 eg = make_float2(__expf(s), __expf(0.2f * s));
        (wh ? g_FH : g_EG)[(size_t)(b * HH + hh) * NN + n0 + r] = eg;
    }
    __syncthreads();

#pragma unroll
    for (int k = 0; k < 2; ++k) {
        int e = t + k * 256;
        int r = e >> 5, c = (e & 31) * 8;
        int hh = c >> 6, o0 = c & 63;
        uint4 v = *reinterpret_cast<const uint4*>(&F_s[r][c]);
        *reinterpret_cast<uint4*>(
            &g_feats16[((size_t)(b * HH + hh) * NN + n0 + r) * FHD + o0]) = v;
    }
}

// ==================== Kernel 2: flash-GAT via mma.sync ====================
extern __shared__ char smem[];

__global__ __launch_bounds__(THR2, 2) void k_attn(
    const float* __restrict__ A, const float* __restrict__ bias,
    float* __restrict__ out) {
    const int b  = blockIdx.y;
    const int i0 = blockIdx.x * TIx;
    const int t = threadIdx.x, lane = t & 31, wid = t >> 5;
    const int h = wid >> 1;            // head
    const int rbase = (wid & 1) * 32;  // warp owns 32 rows
    const int g = lane >> 2;           // frag row group 0..7
    const int q = lane & 3;            // frag col group 0..3
    const uint32_t sb = smem_u32(smem);

    auto issue_tile = [&](int jt, int buf) {
        const uint32_t base = sb + buf * BUFSZ;
        const int j0 = jt * TJx;
#pragma unroll
        for (int k = 0; k < 4; ++k) {            // A: 64x64 f32
            int e = t + k * 256;
            int r = e >> 4, c4 = e & 15;
            CP_ASYNC16(base + OFF_A + r * 288 + c4 * 16,
                       &A[((size_t)(b * NN + i0 + r)) * NN + j0 + c4 * 4]);
        }
#pragma unroll
        for (int k = 0; k < 8; ++k) {            // V: 4x64x64 half
            int e = t + k * 256;
            int hh = e >> 9, j = (e >> 3) & 63, o8 = e & 7;
            CP_ASYNC16(base + OFF_V + hh * 9216 + j * 144 + o8 * 16,
                       &g_feats16[((size_t)(b * HH + hh) * NN + j0 + j) * FHD + o8 * 8]);
        }
        if (t < 128) {                           // FH: 4x64 float2
            int hh = t >> 5, jj = (t & 31) * 2;
            CP_ASYNC16(base + OFF_FH + hh * 512 + jj * 8,
                       &g_FH[(size_t)(b * HH + hh) * NN + j0 + jj]);
        }
        CP_COMMIT();
    };

    // per-thread row constants: E, G for 4 rows
    float Er[2][2], Gr[2][2];
#pragma unroll
    for (int m = 0; m < 2; ++m)
#pragma unroll
        for (int hi = 0; hi < 2; ++hi) {
            float2 eg = g_EG[(size_t)(b * HH + h) * NN + i0 + rbase + m * 16 + g + hi * 8];
            Er[m][hi] = eg.x;
            Gr[m][hi] = eg.y;
        }

    float acc[2][8][4];
#pragma unroll
    for (int m = 0; m < 2; ++m)
#pragma unroll
        for (int n = 0; n < 8; ++n)
#pragma unroll
            for (int c = 0; c < 4; ++c) acc[m][n][c] = 0.f;

    float acc_s[2][4];                 // row-sum accumulators (P @ ones)
#pragma unroll
    for (int m = 0; m < 2; ++m)
#pragma unroll
        for (int c = 0; c < 4; ++c) acc_s[m][c] = 0.f;

    issue_tile(0, 0);

    const int rowlane = lane & 15, colsel = lane >> 4;

#pragma unroll 1
    for (int jt = 0; jt < NJT; ++jt) {
        const int buf = jt & 1;
        if (jt + 1 < NJT) { issue_tile(jt + 1, buf ^ 1); CP_WAIT(1); }
        else             { CP_WAIT(0); }
        __syncthreads();

        const float* As = (const float*)(smem + buf * BUFSZ + OFF_A);
        const float2* FHh = (const float2*)(smem + buf * BUFSZ + OFF_FH) + h * 64;
        const uint32_t sbVh = sb + buf * BUFSZ + OFF_V + h * 9216;

        // ---- build P in mma A-frag layout: p = max(E*F, G*H) * A ----
        uint32_t afr[2][4][4];
#pragma unroll
        for (int k = 0; k < 4; ++k) {
            const int jc = k * 16 + q * 2;
            float2 fh0 = FHh[jc], fh1 = FHh[jc + 1];
            float2 fh8 = FHh[jc + 8], fh9 = FHh[jc + 9];
#pragma unroll
            for (int m = 0; m < 2; ++m) {
                const int rlo = rbase + m * 16 + g;
                float2 alo0 = *(const float2*)(As + rlo * 72 + jc);
                float2 ahi0 = *(const float2*)(As + (rlo + 8) * 72 + jc);
                float2 alo8 = *(const float2*)(As + rlo * 72 + jc + 8);
                float2 ahi8 = *(const float2*)(As + (rlo + 8) * 72 + jc + 8);
                float El = Er[m][0], Gl = Gr[m][0], Eh = Er[m][1], Gh = Gr[m][1];

                float p00 = fmaxf(El * fh0.x, Gl * fh0.y) * alo0.x;
                float p01 = fmaxf(El * fh1.x, Gl * fh1.y) * alo0.y;
                float p10 = fmaxf(Eh * fh0.x, Gh * fh0.y) * ahi0.x;
                float p11 = fmaxf(Eh * fh1.x, Gh * fh1.y) * ahi0.y;
                float p08 = fmaxf(El * fh8.x, Gl * fh8.y) * alo8.x;
                float p09 = fmaxf(El * fh9.x, Gl * fh9.y) * alo8.y;
                float p18 = fmaxf(Eh * fh8.x, Gh * fh8.y) * ahi8.x;
                float p19 = fmaxf(Eh * fh9.x, Gh * fh9.y) * ahi8.y;

                __half2 h0 = __floats2half2_rn(p00, p01);
                __half2 h1 = __floats2half2_rn(p10, p11);
                __half2 h2v = __floats2half2_rn(p08, p09);
                __half2 h3 = __floats2half2_rn(p18, p19);
                afr[m][k][0] = *reinterpret_cast<uint32_t*>(&h0);
                afr[m][k][1] = *reinterpret_cast<uint32_t*>(&h1);
                afr[m][k][2] = *reinterpret_cast<uint32_t*>(&h2v);
                afr[m][k][3] = *reinterpret_cast<uint32_t*>(&h3);
            }
        }

        // ---- P @ V via HMMA, plus P @ ones for the denominator ----
#pragma unroll
        for (int n = 0; n < 4; ++n) {
#pragma unroll
            for (int k = 0; k < 4; ++k) {
                uint32_t bfr[4];
                ldmx4t(bfr, sbVh + (k * 16 + rowlane) * 144 + (n * 16 + colsel * 8) * 2);
#pragma unroll
                for (int m = 0; m < 2; ++m) {
                    mma16816(acc[m][2 * n],     afr[m][k], bfr[0], bfr[1]);
                    mma16816(acc[m][2 * n + 1], afr[m][k], bfr[2], bfr[3]);
                }
            }
        }
#pragma unroll
        for (int k = 0; k < 4; ++k)
#pragma unroll
            for (int m = 0; m < 2; ++m)
                mma16816(acc_s[m], afr[m][k], ONES2, ONES2);
        __syncthreads();
    }

    // ---- denominators: every lane already holds full row sums ----
    float inv[2][2];
#pragma unroll
    for (int m = 0; m < 2; ++m) {
        inv[m][0] = 1.f / acc_s[m][0];   // row rlo
        inv[m][1] = 1.f / acc_s[m][2];   // row rhi
    }

    // ---- epilogue: normalize + bias + relu ----
#pragma unroll
    for (int n = 0; n < 8; ++n) {
        const int col = h * 64 + n * 8 + q * 2;
        float2 bv = *reinterpret_cast<const float2*>(&bias[col]);
#pragma unroll
        for (int m = 0; m < 2; ++m) {
            const int rlo = i0 + rbase + m * 16 + g;
            float2 lo, hi2;
            lo.x  = fmaxf(acc[m][n][0] * inv[m][0] + bv.x, 0.f);
            lo.y  = fmaxf(acc[m][n][1] * inv[m][0] + bv.y, 0.f);
            hi2.x = fmaxf(acc[m][n][2] * inv[m][1] + bv.x, 0.f);
            hi2.y = fmaxf(acc[m][n][3] * inv[m][1] + bv.y, 0.f);
            *reinterpret_cast<float2*>(&out[((size_t)(b * NN + rlo)) * 256 + col]) = lo;
            *reinterpret_cast<float2*>(&out[((size_t)(b * NN + rlo + 8)) * 256 + col]) = hi2;
        }
    }
}

// ==================== launch ====================
extern "C" void kernel_launch(void* const* d_in, const int* in_sizes, int n_in,
                              void* d_out, int out_size) {
    const float* X       = (const float*)d_in[0];
    const float* A       = (const float*)d_in[1];
    const float* W       = (const float*)d_in[2];
    const float* bias    = (const float*)d_in[3];
    const float* a_self  = (const float*)d_in[4];
    const float* a_neigh = (const float*)d_in[5];
    float* out = (float*)d_out;

    static bool attr_set = false;
    if (!attr_set) {
        cudaFuncSetAttribute(k_attn, cudaFuncAttributeMaxDynamicSharedMemorySize, SMEM_SZ);
        attr_set = true;
    }

    k_prep<<<16, 256>>>(W, a_self, a_neigh);
    k_feats<<<BB * NN / 16, 256>>>(X, W);
    dim3 grid2(NN / TIx, BB);
    k_attn<<<grid2, THR2, SMEM_SZ>>>(A, bias, out);
}

// round 8
// speedup vs baseline: 1.5150x; 1.0243x over previous
#include <cuda_runtime.h>
#include <cuda_fp16.h>
#include <cstdint>
#include <math.h>

// ---------------- problem constants ----------------
#define BB 8
#define NN 2048
#define FF 64
#define FHD 64
#define HH 4

#define TIx 64            // rows per CTA
#define TJx 64            // j per tile
#define NJT (NN / TJx)    // 32 j-tiles
#define THR2 256          // k_attn threads (8 warps)

#define ONES2 0x3C003C00u // half2(1.0, 1.0)

// ---------------- scratch ----------------
__device__ __half g_feats16[(size_t)BB * HH * NN * FHD]; // [b][h][n][o] fp16
__device__ float2 g_EG[BB * HH * NN];   // (exp(ss), exp(0.2 ss)) fp32
__device__ __half g_F16[BB * HH * NN];  // exp(sn) half
__device__ __half g_H16[BB * HH * NN];  // exp(0.2 sn) half
__device__ float  g_wa[2 * HH * FF];    // [which][h][f]

// ---------------- helpers ----------------
__device__ __forceinline__ uint32_t smem_u32(const void* p) {
    uint32_t a;
    asm("{ .reg .u64 t; cvta.to.shared.u64 t, %1; cvt.u32.u64 %0, t; }" : "=r"(a) : "l"(p));
    return a;
}
#define CP_ASYNC16(dst, src) \
    asm volatile("cp.async.cg.shared.global [%0], [%1], 16;" :: "r"(dst), "l"(src) : "memory")
#define CP_COMMIT() asm volatile("cp.async.commit_group;" ::: "memory")
#define CP_WAIT(n)  asm volatile("cp.async.wait_group %0;" :: "n"(n) : "memory")

__device__ __forceinline__ void ldmx4t(uint32_t* r, uint32_t addr) {
    asm volatile("ldmatrix.sync.aligned.m8n8.x4.trans.shared.b16 {%0,%1,%2,%3}, [%4];"
                 : "=r"(r[0]), "=r"(r[1]), "=r"(r[2]), "=r"(r[3]) : "r"(addr));
}
__device__ __forceinline__ void mma16816(float* c, const uint32_t* a, uint32_t b0, uint32_t b1) {
    asm volatile(
        "mma.sync.aligned.m16n8k16.row.col.f32.f16.f16.f32 "
        "{%0,%1,%2,%3},{%4,%5,%6,%7},{%8,%9},{%0,%1,%2,%3};"
        : "+f"(c[0]), "+f"(c[1]), "+f"(c[2]), "+f"(c[3])
        : "r"(a[0]), "r"(a[1]), "r"(a[2]), "r"(a[3]), "r"(b0), "r"(b1));
}
__device__ __forceinline__ uint32_t h2bits(__half2 v) {
    return *reinterpret_cast<uint32_t*>(&v);
}

// ---------------- smem layout per buffer (bytes) ----------------
// A: [64][72] f32 (288B pitch), V: [4][64][72] half (144B pitch),
// F: [4][64] half (512B), H: [4][64] half (512B)
#define OFF_A   0
#define OFF_V   18432
#define OFF_F   55296
#define OFF_H   55808
#define BUFSZ   56320
#define SMEM_SZ (2 * BUFSZ)   // 112640 B -> 2 CTAs/SM

// ==================== Kernel 0: wa = W . a ====================
__global__ __launch_bounds__(256) void k_prep(
    const float* __restrict__ W, const float* __restrict__ a_self,
    const float* __restrict__ a_neigh) {
    const int lane = threadIdx.x & 31, wid = threadIdx.x >> 5;
    const int base = blockIdx.x * 32 + wid * 4;
#pragma unroll
    for (int u = 0; u < 4; ++u) {
        int idx = base + u;
        int which = idx >> 8, hf = idx & 255, h = hf >> 6;
        const float* ap = (which ? a_neigh : a_self) + h * 64;
        const float* wrow = W + (size_t)hf * 64;
        float s = wrow[lane] * ap[lane] + wrow[lane + 32] * ap[lane + 32];
#pragma unroll
        for (int d = 16; d > 0; d >>= 1) s += __shfl_xor_sync(0xffffffffu, s, d);
        if (lane == 0) g_wa[idx] = s;
    }
}

// ==================== Kernel 1: feats (fp16) + E/G (fp32) + F/H (half) ====================
__global__ __launch_bounds__(256) void k_feats(
    const float* __restrict__ X, const float* __restrict__ W) {
    const int ROWS = 16;
    int bi = blockIdx.x;
    int b  = bi >> 7;
    int n0 = (bi & 127) * ROWS;
    int t = threadIdx.x;
    int h = t >> 6, o = t & 63;

    __shared__ float X_s[ROWS * 64];
    __shared__ __half F_s[ROWS][256];

    for (int idx = t; idx < ROWS * 64; idx += 256)
        X_s[idx] = X[(size_t)(b * NN + n0 + (idx >> 6)) * FF + (idx & 63)];

    float w_reg[64];
#pragma unroll
    for (int f = 0; f < 64; ++f) w_reg[f] = W[(h * 64 + f) * 64 + o];
    __syncthreads();

#pragma unroll
    for (int r = 0; r < ROWS; ++r) {
        float acc = 0.f;
#pragma unroll
        for (int f = 0; f < 64; ++f) acc += X_s[r * 64 + f] * w_reg[f];
        F_s[r][h * 64 + o] = __float2half(acc);
    }

    if (t < 128) {
        int r = t >> 3, hh = (t >> 1) & 3, wh = t & 1;
        const float* wap = g_wa + wh * 256 + hh * 64;
        float s = 0.f;
#pragma unroll
        for (int f = 0; f < 64; ++f) s += X_s[r * 64 + f] * wap[f];
        size_t idx = (size_t)(b * HH + hh) * NN + n0 + r;
        if (wh) {
            g_F16[idx] = __float2half_rn(__expf(s));
            g_H16[idx] = __float2half_rn(__expf(0.2f * s));
        } else {
            g_EG[idx] = make_float2(__expf(s), __expf(0.2f * s));
        }
    }
    __syncthreads();

#pragma unroll
    for (int k = 0; k < 2; ++k) {
        int e = t + k * 256;
        int r = e >> 5, c = (e & 31) * 8;
        int hh = c >> 6, o0 = c & 63;
        uint4 v = *reinterpret_cast<const uint4*>(&F_s[r][c]);
        *reinterpret_cast<uint4*>(
            &g_feats16[((size_t)(b * HH + hh) * NN + n0 + r) * FHD + o0]) = v;
    }
}

// ==================== Kernel 2: flash-GAT via mma.sync (half2 P-build) ====================
extern __shared__ char smem[];

__global__ __launch_bounds__(THR2, 2) void k_attn(
    const float* __restrict__ A, const float* __restrict__ bias,
    float* __restrict__ out) {
    const int b  = blockIdx.y;
    const int i0 = blockIdx.x * TIx;
    const int t = threadIdx.x, lane = t & 31, wid = t >> 5;
    const int h = wid >> 1;            // head
    const int rbase = (wid & 1) * 32;  // warp owns 32 rows
    const int g = lane >> 2;           // frag row group 0..7
    const int q = lane & 3;            // frag col group 0..3
    const uint32_t sb = smem_u32(smem);

    auto issue_tile = [&](int jt, int buf) {
        const uint32_t base = sb + buf * BUFSZ;
        const int j0 = jt * TJx;
#pragma unroll
        for (int k = 0; k < 4; ++k) {            // A: 64x64 f32
            int e = t + k * 256;
            int r = e >> 4, c4 = e & 15;
            CP_ASYNC16(base + OFF_A + r * 288 + c4 * 16,
                       &A[((size_t)(b * NN + i0 + r)) * NN + j0 + c4 * 4]);
        }
#pragma unroll
        for (int k = 0; k < 8; ++k) {            // V: 4x64x64 half
            int e = t + k * 256;
            int hh = e >> 9, j = (e >> 3) & 63, o8 = e & 7;
            CP_ASYNC16(base + OFF_V + hh * 9216 + j * 144 + o8 * 16,
                       &g_feats16[((size_t)(b * HH + hh) * NN + j0 + j) * FHD + o8 * 8]);
        }
        if (t < 32) {                            // F: 4x64 half
            int hh = t >> 3, jj = (t & 7) * 8;
            CP_ASYNC16(base + OFF_F + hh * 128 + jj * 2,
                       &g_F16[(size_t)(b * HH + hh) * NN + j0 + jj]);
        } else if (t < 64) {                     // H: 4x64 half
            int t2 = t - 32;
            int hh = t2 >> 3, jj = (t2 & 7) * 8;
            CP_ASYNC16(base + OFF_H + hh * 128 + jj * 2,
                       &g_H16[(size_t)(b * HH + hh) * NN + j0 + jj]);
        }
        CP_COMMIT();
    };

    // per-thread row constants as half2 duplicates (loop-invariant)
    __half2 E2d[2][2], G2d[2][2];
#pragma unroll
    for (int m = 0; m < 2; ++m)
#pragma unroll
        for (int hi = 0; hi < 2; ++hi) {
            float2 eg = g_EG[(size_t)(b * HH + h) * NN + i0 + rbase + m * 16 + g + hi * 8];
            E2d[m][hi] = __half2half2(__float2half_rn(eg.x));
            G2d[m][hi] = __half2half2(__float2half_rn(eg.y));
        }

    float acc[2][8][4];
#pragma unroll
    for (int m = 0; m < 2; ++m)
#pragma unroll
        for (int n = 0; n < 8; ++n)
#pragma unroll
            for (int c = 0; c < 4; ++c) acc[m][n][c] = 0.f;

    float acc_s[2][4];                 // row-sum accumulators (P @ ones)
#pragma unroll
    for (int m = 0; m < 2; ++m)
#pragma unroll
        for (int c = 0; c < 4; ++c) acc_s[m][c] = 0.f;

    issue_tile(0, 0);

    const int rowlane = lane & 15, colsel = lane >> 4;

#pragma unroll 1
    for (int jt = 0; jt < NJT; ++jt) {
        const int buf = jt & 1;
        if (jt + 1 < NJT) { issue_tile(jt + 1, buf ^ 1); CP_WAIT(1); }
        else             { CP_WAIT(0); }
        __syncthreads();

        const float* As = (const float*)(smem + buf * BUFSZ + OFF_A);
        const __half2* Fsh = (const __half2*)(smem + buf * BUFSZ + OFF_F) + h * 32;
        const __half2* Hsh = (const __half2*)(smem + buf * BUFSZ + OFF_H) + h * 32;
        const uint32_t sbVh = sb + buf * BUFSZ + OFF_V + h * 9216;

        // ---- build P in mma A-frag layout (half2 SIMD) ----
        uint32_t afr[2][4][4];
#pragma unroll
        for (int k = 0; k < 4; ++k) {
            const int jc = k * 16 + q * 2;
            __half2 F2a = Fsh[jc >> 1], F2b = Fsh[(jc >> 1) + 4];
            __half2 H2a = Hsh[jc >> 1], H2b = Hsh[(jc >> 1) + 4];
#pragma unroll
            for (int m = 0; m < 2; ++m) {
                const int rlo = rbase + m * 16 + g;
                float2 alo0 = *(const float2*)(As + rlo * 72 + jc);
                float2 ahi0 = *(const float2*)(As + (rlo + 8) * 72 + jc);
                float2 alo8 = *(const float2*)(As + rlo * 72 + jc + 8);
                float2 ahi8 = *(const float2*)(As + (rlo + 8) * 72 + jc + 8);

                __half2 a2lo0 = __floats2half2_rn(alo0.x, alo0.y);
                __half2 a2hi0 = __floats2half2_rn(ahi0.x, ahi0.y);
                __half2 a2lo8 = __floats2half2_rn(alo8.x, alo8.y);
                __half2 a2hi8 = __floats2half2_rn(ahi8.x, ahi8.y);

                __half2 El = E2d[m][0], Gl = G2d[m][0];
                __half2 Eh = E2d[m][1], Gh = G2d[m][1];

                afr[m][k][0] = h2bits(__hmul2(
                    __hmax2(__hmul2(El, F2a), __hmul2(Gl, H2a)), a2lo0));
                afr[m][k][1] = h2bits(__hmul2(
                    __hmax2(__hmul2(Eh, F2a), __hmul2(Gh, H2a)), a2hi0));
                afr[m][k][2] = h2bits(__hmul2(
                    __hmax2(__hmul2(El, F2b), __hmul2(Gl, H2b)), a2lo8));
                afr[m][k][3] = h2bits(__hmul2(
                    __hmax2(__hmul2(Eh, F2b), __hmul2(Gh, H2b)), a2hi8));
            }
        }

        // ---- P @ V via HMMA, plus P @ ones for the denominator ----
#pragma unroll
        for (int n = 0; n < 4; ++n) {
#pragma unroll
            for (int k = 0; k < 4; ++k) {
                uint32_t bfr[4];
                ldmx4t(bfr, sbVh + (k * 16 + rowlane) * 144 + (n * 16 + colsel * 8) * 2);
#pragma unroll
                for (int m = 0; m < 2; ++m) {
                    mma16816(acc[m][2 * n],     afr[m][k], bfr[0], bfr[1]);
                    mma16816(acc[m][2 * n + 1], afr[m][k], bfr[2], bfr[3]);
                }
            }
        }
#pragma unroll
        for (int k = 0; k < 4; ++k)
#pragma unroll
            for (int m = 0; m < 2; ++m)
                mma16816(acc_s[m], afr[m][k], ONES2, ONES2);
        __syncthreads();
    }

    // ---- denominators: every lane already holds full row sums ----
    float inv[2][2];
#pragma unroll
    for (int m = 0; m < 2; ++m) {
        inv[m][0] = 1.f / acc_s[m][0];   // row rlo
        inv[m][1] = 1.f / acc_s[m][2];   // row rhi
    }

    // ---- epilogue: normalize + bias + relu ----
#pragma unroll
    for (int n = 0; n < 8; ++n) {
        const int col = h * 64 + n * 8 + q * 2;
        float2 bv = *reinterpret_cast<const float2*>(&bias[col]);
#pragma unroll
        for (int m = 0; m < 2; ++m) {
            const int rlo = i0 + rbase + m * 16 + g;
            float2 lo, hi2;
            lo.x  = fmaxf(acc[m][n][0] * inv[m][0] + bv.x, 0.f);
            lo.y  = fmaxf(acc[m][n][1] * inv[m][0] + bv.y, 0.f);
            hi2.x = fmaxf(acc[m][n][2] * inv[m][1] + bv.x, 0.f);
            hi2.y = fmaxf(acc[m][n][3] * inv[m][1] + bv.y, 0.f);
            *reinterpret_cast<float2*>(&out[((size_t)(b * NN + rlo)) * 256 + col]) = lo;
            *reinterpret_cast<float2*>(&out[((size_t)(b * NN + rlo + 8)) * 256 + col]) = hi2;
        }
    }
}

// ==================== launch ====================
extern "C" void kernel_launch(void* const* d_in, const int* in_sizes, int n_in,
                              void* d_out, int out_size) {
    const float* X       = (const float*)d_in[0];
    const float* A       = (const float*)d_in[1];
    const float* W       = (const float*)d_in[2];
    const float* bias    = (const float*)d_in[3];
    const float* a_self  = (const float*)d_in[4];
    const float* a_neigh = (const float*)d_in[5];
    float* out = (float*)d_out;

    static bool attr_set = false;
    if (!attr_set) {
        cudaFuncSetAttribute(k_attn, cudaFuncAttributeMaxDynamicSharedMemorySize, SMEM_SZ);
        attr_set = true;
    }

    k_prep<<<16, 256>>>(W, a_self, a_neigh);
    k_feats<<<BB * NN / 16, 256>>>(X, W);
    dim3 grid2(NN / TIx, BB);
    k_attn<<<grid2, THR2, SMEM_SZ>>>(A, bias, out);
}